// round 1
// baseline (speedup 1.0000x reference)
#include <cuda_runtime.h>
#include <math.h>

#define B_DIM 256
#define N_DIM 256
#define D_DIM 512
#define MARGIN 0.5f
#define EPS_V 1e-6f
#define ROWS (B_DIM * N_DIM)           // 65536
#define BND ((size_t)ROWS * D_DIM)     // 33554432

// ---- scratch (device globals; no allocation allowed) ----
__device__ float g_dp[ROWS];
__device__ float g_dn[ROWS];
__device__ float g_loss_partial[B_DIM];
__device__ int   g_neg_idx[B_DIM];
__device__ int   g_pos_idx[B_DIM];
__device__ int   g_valid_neg[B_DIM];
__device__ int   g_valid_pos[B_DIM];

// ============================================================
// Kernel 1: per-row L2 distances. One block (128 thr) per (b,n) row.
// Each thread loads one float4 from each of the 3 inputs (D=512 = 128 float4).
// ============================================================
__global__ __launch_bounds__(128) void dist_kernel(
    const float* __restrict__ anchor,
    const float* __restrict__ positive,
    const float* __restrict__ negative)
{
    const int row = blockIdx.x;
    const int t   = threadIdx.x;

    const float4* a4 = (const float4*)(anchor   + (size_t)row * D_DIM);
    const float4* p4 = (const float4*)(positive + (size_t)row * D_DIM);
    const float4* n4 = (const float4*)(negative + (size_t)row * D_DIM);

    float4 av = a4[t];
    float4 pv = p4[t];
    float4 nv = n4[t];

    float dp, dn;
    {
        float x0 = av.x - pv.x + EPS_V, x1 = av.y - pv.y + EPS_V;
        float x2 = av.z - pv.z + EPS_V, x3 = av.w - pv.w + EPS_V;
        dp = x0*x0 + x1*x1 + x2*x2 + x3*x3;
        float y0 = av.x - nv.x + EPS_V, y1 = av.y - nv.y + EPS_V;
        float y2 = av.z - nv.z + EPS_V, y3 = av.w - nv.w + EPS_V;
        dn = y0*y0 + y1*y1 + y2*y2 + y3*y3;
    }

    // warp reduce
    #pragma unroll
    for (int off = 16; off > 0; off >>= 1) {
        dp += __shfl_xor_sync(0xFFFFFFFFu, dp, off);
        dn += __shfl_xor_sync(0xFFFFFFFFu, dn, off);
    }

    __shared__ float s_dp[4], s_dn[4];
    const int wid = t >> 5;
    if ((t & 31) == 0) { s_dp[wid] = dp; s_dn[wid] = dn; }
    __syncthreads();
    if (t == 0) {
        float tp = s_dp[0] + s_dp[1] + s_dp[2] + s_dp[3];
        float tn = s_dn[0] + s_dn[1] + s_dn[2] + s_dn[3];
        g_dp[row] = sqrtf(tp);
        g_dn[row] = sqrtf(tn);
    }
}

// ============================================================
// Kernel 2: per-batch hard mining + loss partials.
// One block (256 thr) per batch b, thread n handles element n.
// argmax/argmin with first-occurrence (lowest index) tie-break.
// ============================================================
__global__ __launch_bounds__(256) void mine_kernel(float* __restrict__ out)
{
    const int b = blockIdx.x;
    const int n = threadIdx.x;

    const float dp = g_dp[b * N_DIM + n];
    const float dn = g_dn[b * N_DIM + n];

    const bool mask_neg = (dp - dn + MARGIN) > 0.0f;
    const bool mask_pos = (dn - dp + MARGIN) > 0.0f;

    __shared__ float s_sn[N_DIM]; __shared__ int s_in[N_DIM];
    __shared__ float s_sp[N_DIM]; __shared__ int s_ip[N_DIM];
    __shared__ float s_l [N_DIM];

    s_sn[n] = mask_neg ? dn : -INFINITY;  s_in[n] = n;
    s_sp[n] = mask_pos ? dp :  INFINITY;  s_ip[n] = n;
    s_l [n] = fmaxf(0.0f, MARGIN + dp - dn);
    __syncthreads();

    for (int off = N_DIM / 2; off > 0; off >>= 1) {
        if (n < off) {
            // argmax of dn (prefer lower index on tie)
            float so = s_sn[n + off]; int io = s_in[n + off];
            if (so > s_sn[n] || (so == s_sn[n] && io < s_in[n])) {
                s_sn[n] = so; s_in[n] = io;
            }
            // argmin of dp (prefer lower index on tie)
            float qo = s_sp[n + off]; int jo = s_ip[n + off];
            if (qo < s_sp[n] || (qo == s_sp[n] && jo < s_ip[n])) {
                s_sp[n] = qo; s_ip[n] = jo;
            }
            s_l[n] += s_l[n + off];
        }
        __syncthreads();
    }

    if (n == 0) {
        const int vn = (s_sn[0] > -INFINITY) ? 1 : 0;
        const int vp = (s_sp[0] <  INFINITY) ? 1 : 0;
        g_neg_idx[b] = s_in[0];
        g_pos_idx[b] = s_ip[0];
        g_valid_neg[b] = vn;
        g_valid_pos[b] = vp;
        g_loss_partial[b] = s_l[0];
        // valid flags straight into output (as float 0/1)
        out[1 + 2 * BND + b]         = (float)vn;
        out[1 + 2 * BND + B_DIM + b] = (float)vp;
    }
}

// ============================================================
// Kernel 3: deterministic loss finalize (single block).
// ============================================================
__global__ __launch_bounds__(256) void loss_kernel(float* __restrict__ out)
{
    const int t = threadIdx.x;
    __shared__ float s[B_DIM];
    s[t] = g_loss_partial[t];
    __syncthreads();
    for (int off = B_DIM / 2; off > 0; off >>= 1) {
        if (t < off) s[t] += s[t + off];
        __syncthreads();
    }
    if (t == 0) out[0] = s[0] * (1.0f / (float)(B_DIM * N_DIM));
}

// ============================================================
// Kernel 4: gather + write hard_neg / hard_pos.
// One block (128 thr) per (b,n) row; scalar coalesced loads/stores
// (output base +1 float breaks 16B alignment).
// ============================================================
__global__ __launch_bounds__(128) void gather_kernel(
    const float* __restrict__ positive,
    const float* __restrict__ negative,
    float* __restrict__ out)
{
    const int row = blockIdx.x;
    const int b = row >> 8;       // N_DIM == 256
    const int n = row & (N_DIM - 1);
    const int t = threadIdx.x;

    const int  ni = g_neg_idx[b];
    const int  pi = g_pos_idx[b];
    const bool vn = g_valid_neg[b] != 0;
    const bool vp = g_valid_pos[b] != 0;

    // N-index used as BATCH index (faithful to reference)
    const float* nsrc = negative + ((size_t)ni * N_DIM + n) * D_DIM;
    const float* psrc = positive + ((size_t)pi * N_DIM + n) * D_DIM;

    float* hn = out + 1 +       (size_t)row * D_DIM;
    float* hp = out + 1 + BND + (size_t)row * D_DIM;

    #pragma unroll
    for (int i = t; i < D_DIM; i += 128) {
        hn[i] = vn ? __ldg(&nsrc[i]) : 0.0f;
        hp[i] = vp ? __ldg(&psrc[i]) : 0.0f;
    }
}

// ============================================================
extern "C" void kernel_launch(void* const* d_in, const int* in_sizes, int n_in,
                              void* d_out, int out_size)
{
    const float* anchor   = (const float*)d_in[0];
    const float* positive = (const float*)d_in[1];
    const float* negative = (const float*)d_in[2];
    float* out = (float*)d_out;

    dist_kernel  <<<ROWS, 128>>>(anchor, positive, negative);
    mine_kernel  <<<B_DIM, 256>>>(out);
    loss_kernel  <<<1, 256>>>(out);
    gather_kernel<<<ROWS, 128>>>(positive, negative, out);
}